// round 2
// baseline (speedup 1.0000x reference)
#include <cuda_runtime.h>
#include <cuda_bf16.h>
#include <math.h>

#define BB   4      // batch
#define KH   18     // harmonics
#define KHP  19     // padded float2 row stride (odd -> conflict-free LDS.64)
#define TPB  128

__global__ __launch_bounds__(TPB, 11) void dddm_kernel(
    const float* __restrict__ t_in,
    const float* __restrict__ poly,
    const float* __restrict__ fa,
    const float* __restrict__ fb,
    const int*   __restrict__ stage_p,
    float*       __restrict__ out,
    int N)
{
    __shared__ float2 tbl[BB][KH];        // (cos, sin); zeroed when band inactive
    __shared__ float  tsh[BB];
    __shared__ float2 sAB[TPB * KHP];     // interleaved (a,b) per point, padded

    const int tid = threadIdx.x;
    const int block_base = blockIdx.x * TPB;

    // ---- per-block tiny setup: trig table + t values (uniform work) ----
    if (tid < BB * KH) {
        const int b = tid / KH;
        const int k = tid % KH;
        float t = t_in[b];
        if (k == 0) tsh[b] = t;
        int st = stage_p ? stage_p[0] : 3;
        int cs = (st < 0) ? 3 : (st > 3 ? 3 : st);
        int req = (k < 3) ? 1 : ((k < 9) ? 2 : 3);
        // phase = 2*pi*(k+1)*t ; fold (k+1)*t into [0,1) so sincosf stays
        // in its accurate range.
        float x = (float)(k + 1) * t;
        x -= floorf(x);
        float s, c;
        sincosf(6.28318530717958647692f * x, &s, &c);
        bool act = (cs >= req);
        tbl[b][k] = make_float2(act ? c : 0.0f, act ? s : 0.0f);
    }

    // ---- stage fourier_a / fourier_b into shared, coalesced float4 loads ----
    const int nvalid = min(TPB, N - block_base);
    const int velems = nvalid * KH;                 // floats per array this tile
    const size_t base = (size_t)block_base * KH;    // 16B-aligned (128*18*4/blk)

    const int v4 = velems & ~3;
    for (int i = tid * 4; i < v4; i += TPB * 4) {
        float4 va = __ldcs((const float4*)(fa + base + i));
        float4 vb = __ldcs((const float4*)(fb + base + i));
        int r = i / KH;
        int k = i - r * KH;
        #pragma unroll
        for (int e = 0; e < 4; ++e) {
            float av = (e == 0) ? va.x : (e == 1) ? va.y : (e == 2) ? va.z : va.w;
            float bv = (e == 0) ? vb.x : (e == 1) ? vb.y : (e == 2) ? vb.z : vb.w;
            sAB[r * KHP + k] = make_float2(av, bv);
            if (++k == KH) { k = 0; ++r; }
        }
    }
    for (int i = v4 + tid; i < velems; i += TPB) {  // scalar tail (partial blocks)
        int r = i / KH;
        int k = i - r * KH;
        sAB[r * KHP + k] = make_float2(__ldcs(fa + base + i), __ldcs(fb + base + i));
    }

    __syncthreads();

    // ---- per-point compute ----
    const int n = block_base + tid;
    if (n < N) {
        float4 pc = __ldcs((const float4*)(poly + (size_t)n * 4));

        float accp[BB];
        float accf[BB];
        #pragma unroll
        for (int b = 0; b < BB; ++b) {
            float t = tsh[b];
            // c0 + c1 t + c2 t^2 + c3 t^3 (Horner)
            accp[b] = fmaf(fmaf(fmaf(pc.w, t, pc.z), t, pc.y), t, pc.x);
            accf[b] = 0.0f;
        }

        const float2* __restrict__ row = sAB + tid * KHP;
        #pragma unroll
        for (int k = 0; k < KH; ++k) {
            float2 ab = row[k];                  // conflict-free LDS.64
            #pragma unroll
            for (int b = 0; b < BB; ++b) {
                float2 w = tbl[b][k];            // warp-uniform broadcast
                accf[b] = fmaf(ab.x, w.x, accf[b]);
                accf[b] = fmaf(ab.y, w.y, accf[b]);
            }
        }

        const size_t NN = (size_t)N;
        #pragma unroll
        for (int b = 0; b < BB; ++b) {
            __stcs(out + (size_t)b * NN + n, accp[b]);                   // y_poly
            __stcs(out + (size_t)BB * NN + (size_t)b * NN + n, accf[b]); // y_fourier
        }
    }
}

extern "C" void kernel_launch(void* const* d_in, const int* in_sizes, int n_in,
                              void* d_out, int out_size)
{
    const float* t_in  = (const float*)d_in[0];
    const float* poly  = (const float*)d_in[1];
    const float* fa    = (const float*)d_in[2];
    const float* fb    = (const float*)d_in[3];
    const int*   stage = (n_in > 4) ? (const int*)d_in[4] : nullptr;

    const int N = in_sizes[1] / 4;     // poly_coeffs is [N, 4]
    float* outp = (float*)d_out;

    const int grid = (N + TPB - 1) / TPB;
    dddm_kernel<<<grid, TPB>>>(t_in, poly, fa, fb, stage, outp, N);
}

// round 3
// speedup vs baseline: 1.5085x; 1.5085x over previous
#include <cuda_runtime.h>
#include <cuda_bf16.h>
#include <math.h>

#define BB   4      // batch
#define KH   18     // harmonics
#define TPB  256    // N = 128^3 is divisible by 256

#define TILE_F   (TPB * KH)        // floats per tile per array (4608)
#define TILE_F4  (TILE_F / 4)      // float4 per tile per array (1152)
#define NIT      ((TILE_F4 + TPB - 1) / TPB)   // 5 staging iters (last partial)

__global__ __launch_bounds__(TPB) void dddm_kernel(
    const float* __restrict__ t_in,
    const float* __restrict__ poly,
    const float* __restrict__ fa,
    const float* __restrict__ fb,
    const int*   __restrict__ stage_p,
    float*       __restrict__ out,
    int N)
{
    __shared__ float2 tbl[BB][KH];   // (cos, sin); zeroed when band inactive
    __shared__ float  tsh[BB];
    __shared__ float  sA[TILE_F];    // raw linear copy of fa tile
    __shared__ float  sB[TILE_F];    // raw linear copy of fb tile

    const int tid = threadIdx.x;
    const int block_base = blockIdx.x * TPB;

    // ---- per-block tiny setup: trig table + t values (uniform work) ----
    if (tid < BB * KH) {
        const int b = tid / KH;
        const int k = tid % KH;
        float t = t_in[b];
        if (k == 0) tsh[b] = t;
        int st = stage_p ? stage_p[0] : 3;
        int cs = (st < 0) ? 3 : (st > 3 ? 3 : st);
        int req = (k < 3) ? 1 : ((k < 9) ? 2 : 3);
        // phase = 2*pi*(k+1)*t ; fold (k+1)*t into [0,1) so sincosf stays
        // in its accurate range.
        float x = (float)(k + 1) * t;
        x -= floorf(x);
        float s, c;
        sincosf(6.28318530717958647692f * x, &s, &c);
        bool act = (cs >= req);
        tbl[b][k] = make_float2(act ? c : 0.0f, act ? s : 0.0f);
    }

    // ---- stage fourier tiles: coalesced LDG.128 -> conflict-free STS.128 ----
    const size_t base = (size_t)block_base * KH;
    if (block_base + TPB <= N) {
        const float4* __restrict__ fa4 = (const float4*)(fa + base);
        const float4* __restrict__ fb4 = (const float4*)(fb + base);
        float4* __restrict__ sA4 = (float4*)sA;
        float4* __restrict__ sB4 = (float4*)sB;
        #pragma unroll
        for (int it = 0; it < NIT; ++it) {
            int i = tid + it * TPB;
            if (i < TILE_F4) {       // compile-time-resolvable except last iter
                sA4[i] = fa4[i];
                sB4[i] = fb4[i];
            }
        }
    } else {                          // generic tail block (unused for 128^3)
        const int velems = (N - block_base) * KH;
        for (int i = tid; i < velems; i += TPB) {
            sA[i] = fa[base + i];
            sB[i] = fb[base + i];
        }
    }

    __syncthreads();

    // ---- per-point compute ----
    const int n = block_base + tid;
    if (n < N) {
        float4 pc = *(const float4*)(poly + (size_t)n * 4);

        float accp[BB];
        float accf[BB];
        #pragma unroll
        for (int b = 0; b < BB; ++b) {
            float t = tsh[b];
            // c0 + c1 t + c2 t^2 + c3 t^3 (Horner)
            accp[b] = fmaf(fmaf(fmaf(pc.w, t, pc.z), t, pc.y), t, pc.x);
            accf[b] = 0.0f;
        }

        // row start = tid*18 floats (even -> float2-aligned); lane stride of
        // 18 floats hits 16 distinct even banks -> conflict-free LDS.64
        const float2* __restrict__ rowA = (const float2*)(sA + tid * KH);
        const float2* __restrict__ rowB = (const float2*)(sB + tid * KH);

        #pragma unroll
        for (int kk = 0; kk < KH / 2; ++kk) {
            float2 a2 = rowA[kk];    // a[2kk], a[2kk+1]
            float2 b2 = rowB[kk];    // b[2kk], b[2kk+1]
            #pragma unroll
            for (int b = 0; b < BB; ++b) {
                float2 w0 = tbl[b][2 * kk];       // (cos, sin) harmonic 2kk
                float2 w1 = tbl[b][2 * kk + 1];   // (cos, sin) harmonic 2kk+1
                accf[b] = fmaf(a2.x, w0.x, accf[b]);
                accf[b] = fmaf(b2.x, w0.y, accf[b]);
                accf[b] = fmaf(a2.y, w1.x, accf[b]);
                accf[b] = fmaf(b2.y, w1.y, accf[b]);
            }
        }

        const size_t NN = (size_t)N;
        #pragma unroll
        for (int b = 0; b < BB; ++b) {
            out[(size_t)b * NN + n] = accp[b];                   // y_poly
            out[(size_t)(BB + b) * NN + n] = accf[b];            // y_fourier
        }
    }
}

extern "C" void kernel_launch(void* const* d_in, const int* in_sizes, int n_in,
                              void* d_out, int out_size)
{
    const float* t_in  = (const float*)d_in[0];
    const float* poly  = (const float*)d_in[1];
    const float* fa    = (const float*)d_in[2];
    const float* fb    = (const float*)d_in[3];
    const int*   stage = (n_in > 4) ? (const int*)d_in[4] : nullptr;

    const int N = in_sizes[1] / 4;     // poly_coeffs is [N, 4]
    float* outp = (float*)d_out;

    const int grid = (N + TPB - 1) / TPB;
    dddm_kernel<<<grid, TPB>>>(t_in, poly, fa, fb, stage, outp, N);
}